// round 1
// baseline (speedup 1.0000x reference)
#include <cuda_runtime.h>

// Problem constants
#define N_IMG 16384
#define SS 49
#define NCELL (N_IMG * SS)          // 802816
#define F 30                        // 20 probs + 2 conf + 8 box
#define CPB 128                     // cells per block (NCELL % CPB == 0 -> 6272 blocks)

__device__ double g_acc;

__global__ void zero_acc_kernel() {
    g_acc = 0.0;
}

__global__ __launch_bounds__(CPB) void loss_kernel(const float* __restrict__ preds,
                                                   const float* __restrict__ targets) {
    __shared__ float sp[CPB * F];
    __shared__ float st[CPB * F];
    __shared__ float warp_sums[CPB / 32];

    const long long base = (long long)blockIdx.x * (CPB * F);

    // Cooperative coalesced float4 staging. Chunk base is 30720*blockIdx bytes,
    // 16B-aligned, and CPB*F = 3840 floats = 960 float4 per tensor.
    const float4* __restrict__ p4 = reinterpret_cast<const float4*>(preds + base);
    const float4* __restrict__ t4 = reinterpret_cast<const float4*>(targets + base);
    float4* sp4 = reinterpret_cast<float4*>(sp);
    float4* st4 = reinterpret_cast<float4*>(st);
    const int n4 = CPB * F / 4;  // 960
#pragma unroll
    for (int i = threadIdx.x; i < n4; i += CPB) {
        sp4[i] = p4[i];
        st4[i] = t4[i];
    }
    __syncthreads();

    const float* p = sp + threadIdx.x * F;
    const float* t = st + threadIdx.x * F;

    // conf MSE term (always): NOOBJ * sum((p_conf - t_conf)^2)
    float pc0 = p[20], pc1 = p[21];
    float tc0 = t[20], tc1 = t[21];
    float d0 = pc0 - tc0, d1 = pc1 - tc1;
    float l = 0.5f * (d0 * d0 + d1 * d1);

    if (tc0 > 0.0f) {  // obj cell
        // class-prob MSE
        float s = 0.0f;
#pragma unroll
        for (int c = 0; c < 20; c++) {
            float d = p[c] - t[c];
            s += d * d;
        }
        l += s;

        // IoU of both predicted boxes vs target boxes
        float iou0, iou1;
#pragma unroll
        for (int b = 0; b < 2; b++) {
            const float* pb = p + 22 + 4 * b;
            const float* tb = t + 22 + 4 * b;
            float xA = fmaxf(pb[0] - pb[2] * 0.5f, tb[0] - tb[2] * 0.5f);
            float yA = fmaxf(pb[1] - pb[3] * 0.5f, tb[1] - tb[3] * 0.5f);
            float xB = fminf(pb[0] + pb[2] * 0.5f, tb[0] + tb[2] * 0.5f);
            float yB = fminf(pb[1] + pb[3] * 0.5f, tb[1] + tb[3] * 0.5f);
            float inter = fmaxf(0.0f, xB - xA) * fmaxf(0.0f, yB - yA);
            float areaA = pb[2] * pb[3];
            float areaB = tb[2] * tb[3];
            float iou = inter / (areaA + areaB - inter);
            if (b == 0) iou0 = iou; else iou1 = iou;
        }
        // argmax with first-index tie-break -> strict >
        int best = (iou1 > iou0) ? 1 : 0;

        // responsible-box confidence term: (1 - NOOBJ) * (pc - 1)^2  (tc == 1 when obj)
        float pc = best ? pc1 : pc0;
        float dc = pc - 1.0f;
        l += 0.5f * dc * dc;

        // coord term: COORD * ((x)^2 + (y)^2 + (sqrt w)^2 + (sqrt h)^2)
        const float* pb = p + 22 + 4 * best;
        const float* tb = t + 22 + 4 * best;
        float dx = pb[0] - tb[0];
        float dy = pb[1] - tb[1];
        float dw = sqrtf(pb[2]) - sqrtf(tb[2]);
        float dh = sqrtf(pb[3]) - sqrtf(tb[3]);
        l += 5.0f * (dx * dx + dy * dy + dw * dw + dh * dh);
    }

    // warp reduction
#pragma unroll
    for (int off = 16; off > 0; off >>= 1)
        l += __shfl_down_sync(0xffffffffu, l, off);
    if ((threadIdx.x & 31) == 0)
        warp_sums[threadIdx.x >> 5] = l;
    __syncthreads();
    if (threadIdx.x == 0) {
        float blk = warp_sums[0] + warp_sums[1] + warp_sums[2] + warp_sums[3];
        atomicAdd(&g_acc, (double)blk);
    }
}

__global__ void finalize_kernel(float* __restrict__ out) {
    out[0] = (float)(g_acc / (double)N_IMG);
}

extern "C" void kernel_launch(void* const* d_in, const int* in_sizes, int n_in,
                              void* d_out, int out_size) {
    const float* preds = (const float*)d_in[0];
    const float* targets = (const float*)d_in[1];
    float* out = (float*)d_out;

    zero_acc_kernel<<<1, 1>>>();
    loss_kernel<<<NCELL / CPB, CPB>>>(preds, targets);
    finalize_kernel<<<1, 1>>>(out);
}